// round 2
// baseline (speedup 1.0000x reference)
#include <cuda_runtime.h>

#define H 512
#define W 512
#define MASK 511
#define NPLANE (H * W)

#define K_IT 10                  // Jacobi iterations per launch
#define NLAUNCH 100              // K_IT * NLAUNCH = 1000
#define TILE 32                  // output tile (square)
#define R (TILE + 2 * K_IT)      // 52: region with halo
#define RR (R * R)               // 2704
#define R4 (R / 4)               // 13 float4 groups per row
#define NTHREADS 256

__device__ float g_partial[2 * NPLANE];
__device__ float g_B[NPLANE];
__device__ float g_phi[2][NPLANE];

// K1: partial[c] = -(u*ddx(X[c]) + v*ddy(X[c])) + NU*lap(X[c]) + forcing[c]
__global__ void k_partial(const float* __restrict__ X, const float* __restrict__ F) {
    int id = blockIdx.x * blockDim.x + threadIdx.x;
    if (id >= NPLANE) return;
    int i = id >> 9, j = id & MASK;
    int im = (i - 1) & MASK, ip = (i + 1) & MASK;
    int jm = (j - 1) & MASK, jp = (j + 1) & MASK;

    float u = X[id];
    float v = X[NPLANE + id];
    const float NU = 0.1f;
#pragma unroll
    for (int c = 0; c < 2; ++c) {
        const float* xc = X + c * NPLANE;
        float ctr = xc[id];
        float up = xc[im * W + j];
        float dn = xc[ip * W + j];
        float lf = xc[i * W + jm];
        float rt = xc[i * W + jp];
        float dx = (dn - up) * 0.5f;
        float dy = (rt - lf) * 0.5f;
        float lap = (up + dn + lf + rt) - 4.0f * ctr;
        g_partial[c * NPLANE + id] = -(u * dx + v * dy) + NU * lap + F[c * NPLANE + id];
    }
}

// K2: B = RHO*(ddx(p0)+ddy(p1))/DT ; phi[0] = B
__global__ void k_rhs() {
    int id = blockIdx.x * blockDim.x + threadIdx.x;
    if (id >= NPLANE) return;
    int i = id >> 9, j = id & MASK;
    int im = (i - 1) & MASK, ip = (i + 1) & MASK;
    int jm = (j - 1) & MASK, jp = (j + 1) & MASK;

    const float* p0 = g_partial;
    const float* p1 = g_partial + NPLANE;
    float b = ((p0[ip * W + j] - p0[im * W + j]) + (p1[i * W + jp] - p1[i * W + jm])) * 5.0f;
    g_B[id] = b;
    g_phi[0][id] = b;
}

// K3: temporally-blocked Jacobi: K_IT sweeps per launch.
// Reads g_phi[p], writes inner TILE x TILE of g_phi[p^1].
__global__ void __launch_bounds__(NTHREADS) k_jacobi_tb(int p) {
    __shared__ float s0[RR];
    __shared__ float s1[RR];
    __shared__ float sb[RR];

    const float* __restrict__ src = g_phi[p];
    float* __restrict__ dst = g_phi[p ^ 1];
    const int bi = blockIdx.y * TILE;   // global row of output tile origin
    const int bj = blockIdx.x * TILE;   // global col
    const int tid = threadIdx.x;

    // Load (TILE+2K)^2 region with periodic wrap, plus B region
    for (int idx = tid; idx < RR; idx += NTHREADS) {
        int i = idx / R, j = idx - i * R;
        int gi = (bi - K_IT + i) & MASK;
        int gj = (bj - K_IT + j) & MASK;
        int g = gi * W + gj;
        s0[idx] = src[g];
        sb[idx] = g_B[g];
    }
    __syncthreads();

    float* a = s0;
    float* b = s1;
#pragma unroll
    for (int t = 0; t < K_IT; ++t) {
        // Update rows 1..R-2, all columns in aligned float4 groups.
        // Cells within distance t of the region edge become garbage; the
        // output tile is at distance >= K_IT, so it is exact.
        for (int g = tid; g < (R - 2) * R4; g += NTHREADS) {
            int i = 1 + g / R4;
            int j4 = (g - (i - 1) * R4) * 4;
            int base = i * R + j4;
            float4 up = *(const float4*)(a + base - R);
            float4 dn = *(const float4*)(a + base + R);
            float4 ce = *(const float4*)(a + base);
            float lf = a[base - 1];       // in-bounds: base >= R, so base-1 >= R-1
            float rt = a[base + 4];       // in-bounds for i <= R-2
            float4 bb = *(const float4*)(sb + base);
            float4 o;
            o.x = (up.x + dn.x + lf   + ce.y - bb.x) * 0.25f;
            o.y = (up.y + dn.y + ce.x + ce.z - bb.y) * 0.25f;
            o.z = (up.z + dn.z + ce.y + ce.w - bb.z) * 0.25f;
            o.w = (up.w + dn.w + ce.z + rt   - bb.w) * 0.25f;
            *(float4*)(b + base) = o;
        }
        __syncthreads();
        float* tmp = a; a = b; b = tmp;
    }

    // Write inner tile (rows/cols K_IT .. K_IT+TILE-1); no wrap needed.
    for (int idx = tid; idx < TILE * TILE; idx += NTHREADS) {
        int i = idx >> 5;          // TILE == 32
        int j = idx & 31;
        dst[(bi + i) * W + (bj + j)] = a[(K_IT + i) * R + (K_IT + j)];
    }
}

// K4: out[c] = partial[c] - grad(phi)[c]
__global__ void k_out(float* __restrict__ out) {
    int id = blockIdx.x * blockDim.x + threadIdx.x;
    if (id >= NPLANE) return;
    int i = id >> 9, j = id & MASK;
    int im = (i - 1) & MASK, ip = (i + 1) & MASK;
    int jm = (j - 1) & MASK, jp = (j + 1) & MASK;

    const float* phi = g_phi[0];   // NLAUNCH even -> final result in buffer 0
    float gx = (phi[ip * W + j] - phi[im * W + j]) * 0.5f;
    float gy = (phi[i * W + jp] - phi[i * W + jm]) * 0.5f;
    out[id]          = g_partial[id]          - gx;
    out[NPLANE + id] = g_partial[NPLANE + id] - gy;
}

extern "C" void kernel_launch(void* const* d_in, const int* in_sizes, int n_in,
                              void* d_out, int out_size) {
    const float* X = (const float*)d_in[1];
    const float* F = (const float*)d_in[2];
    float* out = (float*)d_out;

    const int threads = 256;
    const int blocks = (NPLANE + threads - 1) / threads;
    dim3 jgrid(W / TILE, H / TILE);

    k_partial<<<blocks, threads>>>(X, F);
    k_rhs<<<blocks, threads>>>();
    for (int l = 0; l < NLAUNCH; ++l) {
        k_jacobi_tb<<<jgrid, NTHREADS>>>(l & 1);
    }
    k_out<<<blocks, threads>>>(out);
}

// round 3
// speedup vs baseline: 37.4061x; 37.4061x over previous
#include <cuda_runtime.h>

#define H 512
#define W 512
#define MASK 511
#define NPLANE (H * W)
#define NTH 256

__device__ float  g_partial[2 * NPLANE];
__device__ float  g_B[NPLANE];
__device__ float  g_phi[NPLANE];
__device__ float2 g_Fhat[NPLANE];

// ---------------------------------------------------------------- setup
__global__ void k_partial(const float* __restrict__ X, const float* __restrict__ F) {
    int id = blockIdx.x * blockDim.x + threadIdx.x;
    if (id >= NPLANE) return;
    int i = id >> 9, j = id & MASK;
    int im = (i - 1) & MASK, ip = (i + 1) & MASK;
    int jm = (j - 1) & MASK, jp = (j + 1) & MASK;

    float u = X[id];
    float v = X[NPLANE + id];
    const float NU = 0.1f;
#pragma unroll
    for (int c = 0; c < 2; ++c) {
        const float* xc = X + c * NPLANE;
        float ctr = xc[id];
        float up = xc[im * W + j];
        float dn = xc[ip * W + j];
        float lf = xc[i * W + jm];
        float rt = xc[i * W + jp];
        float dx = (dn - up) * 0.5f;
        float dy = (rt - lf) * 0.5f;
        float lap = (up + dn + lf + rt) - 4.0f * ctr;
        g_partial[c * NPLANE + id] = -(u * dx + v * dy) + NU * lap + F[c * NPLANE + id];
    }
}

__global__ void k_rhs() {
    int id = blockIdx.x * blockDim.x + threadIdx.x;
    if (id >= NPLANE) return;
    int i = id >> 9, j = id & MASK;
    int im = (i - 1) & MASK, ip = (i + 1) & MASK;
    int jm = (j - 1) & MASK, jp = (j + 1) & MASK;

    const float* p0 = g_partial;
    const float* p1 = g_partial + NPLANE;
    // RHO/(2*DX*DT) = 5
    g_B[id] = ((p0[ip * W + j] - p0[im * W + j]) + (p1[i * W + jp] - p1[i * W + jm])) * 5.0f;
}

// ---------------------------------------------------------------- FFT core
// 512-point Stockham radix-2 C2C FFT, 256 threads, DIF autosort.
// SIGN = -1 forward, +1 inverse (unnormalized). Result ends in buffer y.
template <int SIGN>
__device__ __forceinline__ float2* fft512(float2* x, float2* y, int tid) {
    float2* src = x;
    float2* dst = y;
    int n = 512, s = 1;
#pragma unroll
    for (int stage = 0; stage < 9; ++stage) {
        int m = n >> 1;
        int p = tid >> stage;
        int q = tid & (s - 1);
        float ang = (float)SIGN * 6.283185307179586f * (float)p / (float)n;
        float sn, cs;
        sincosf(ang, &sn, &cs);
        float2 a = src[q + s * p];
        float2 b = src[q + s * p + s * m];
        float2 d = make_float2(a.x - b.x, a.y - b.y);
        dst[q + 2 * s * p]     = make_float2(a.x + b.x, a.y + b.y);
        dst[q + 2 * s * p + s] = make_float2(d.x * cs - d.y * sn, d.x * sn + d.y * cs);
        __syncthreads();
        float2* t = src; src = dst; dst = t;
        n >>= 1; s <<= 1;
    }
    return src;  // after 9 swaps this is the original y
}

// Transfer function for 1000 Jacobi iterations, incl. 1/N^2 IFFT normalization.
__device__ __forceinline__ float jacobi_T(int ki, int kj) {
    const float invN2 = 1.0f / 262144.0f;
    float ha = 0.0061359231515f * (float)ki;   // pi*ki/512
    float hb = 0.0061359231515f * (float)kj;
    float sa = sinf(ha), sb = sinf(hb);
    float oms = sa * sa + sb * sb;             // 1 - s, computed without cancellation
    if (oms <= 0.0f) return -249.0f * invN2;   // s == 1 (ki=kj=0)
    // s^1000 = ((1-oms)^2)^500 = exp(500*log1p(-oms*(2-oms)))
    float arg = 500.0f * log1pf(-oms * (2.0f - oms));
    float s1000 = (arg < -87.0f) ? 0.0f : expf(arg);
    return (s1000 - (1.0f - s1000) / (4.0f * oms)) * invN2;
}

// Forward FFT along rows (contiguous axis j): B(real) -> g_Fhat
__global__ void __launch_bounds__(NTH) k_fft_rows_fwd() {
    __shared__ float2 A[512], Bb[512];
    int r = blockIdx.x, t = threadIdx.x;
    A[t]       = make_float2(g_B[r * W + t], 0.0f);
    A[t + 256] = make_float2(g_B[r * W + t + 256], 0.0f);
    __syncthreads();
    float2* res = fft512<-1>(A, Bb, t);
    g_Fhat[r * W + t]       = res[t];
    g_Fhat[r * W + t + 256] = res[t + 256];
}

// Per column: forward FFT along i, multiply by T(ki,kj)/N^2, inverse FFT along i.
__global__ void __launch_bounds__(NTH) k_fft_cols_T() {
    __shared__ float2 A[512], Bb[512];
    int c = blockIdx.x, t = threadIdx.x;
    A[t]       = g_Fhat[t * W + c];
    A[t + 256] = g_Fhat[(t + 256) * W + c];
    __syncthreads();
    float2* res = fft512<-1>(A, Bb, t);   // res == Bb

    float T0 = jacobi_T(t, c);
    float T1 = jacobi_T(t + 256, c);
    float2 v0 = res[t], v1 = res[t + 256];
    res[t]       = make_float2(v0.x * T0, v0.y * T0);
    res[t + 256] = make_float2(v1.x * T1, v1.y * T1);
    __syncthreads();

    float2* out = fft512<1>(res, A, t);   // inverse along i; out == A
    g_Fhat[t * W + c]         = out[t];
    g_Fhat[(t + 256) * W + c] = out[t + 256];
}

// Inverse FFT along rows; real part -> phi
__global__ void __launch_bounds__(NTH) k_fft_rows_inv() {
    __shared__ float2 A[512], Bb[512];
    int r = blockIdx.x, t = threadIdx.x;
    A[t]       = g_Fhat[r * W + t];
    A[t + 256] = g_Fhat[r * W + t + 256];
    __syncthreads();
    float2* res = fft512<1>(A, Bb, t);
    g_phi[r * W + t]       = res[t].x;
    g_phi[r * W + t + 256] = res[t + 256].x;
}

// ---------------------------------------------------------------- epilogue
__global__ void k_out(float* __restrict__ out) {
    int id = blockIdx.x * blockDim.x + threadIdx.x;
    if (id >= NPLANE) return;
    int i = id >> 9, j = id & MASK;
    int im = (i - 1) & MASK, ip = (i + 1) & MASK;
    int jm = (j - 1) & MASK, jp = (j + 1) & MASK;

    float gx = (g_phi[ip * W + j] - g_phi[im * W + j]) * 0.5f;
    float gy = (g_phi[i * W + jp] - g_phi[i * W + jm]) * 0.5f;
    out[id]          = g_partial[id]          - gx;
    out[NPLANE + id] = g_partial[NPLANE + id] - gy;
}

extern "C" void kernel_launch(void* const* d_in, const int* in_sizes, int n_in,
                              void* d_out, int out_size) {
    const float* X = (const float*)d_in[1];
    const float* F = (const float*)d_in[2];
    float* out = (float*)d_out;

    const int blocks = NPLANE / NTH;
    k_partial<<<blocks, NTH>>>(X, F);
    k_rhs<<<blocks, NTH>>>();
    k_fft_rows_fwd<<<H, NTH>>>();
    k_fft_cols_T<<<W, NTH>>>();
    k_fft_rows_inv<<<H, NTH>>>();
    k_out<<<blocks, NTH>>>(out);
}

// round 4
// speedup vs baseline: 53.6091x; 1.4332x over previous
#include <cuda_runtime.h>

#define H 512
#define W 512
#define MASK 511
#define NPLANE (H * W)
#define NTH 256

#define FSTRIDE 580              // float2 stride per sub-FFT (bank-offset 8f)
#define PAD(i) ((i) + ((i) >> 3))

__device__ float  g_partial[2 * NPLANE];
__device__ float2 g_Fhat[NPLANE];

__device__ __forceinline__ float2 cmul(float2 a, float2 b) {
    return make_float2(a.x * b.x - a.y * b.y, a.x * b.y + a.y * b.x);
}
__device__ __forceinline__ float2 cadd(float2 a, float2 b) { return make_float2(a.x + b.x, a.y + b.y); }
__device__ __forceinline__ float2 csub(float2 a, float2 b) { return make_float2(a.x - b.x, a.y - b.y); }

// 8-point DFT, natural order in/out, constant twiddles. SIGN=-1 forward.
template <int SIGN>
__device__ __forceinline__ void dft8(const float2* a, float2* y) {
    const float C = 0.70710678118654752f;
    const float S = (float)SIGN;
    float2 u[8], v[8];
#pragma unroll
    for (int p = 0; p < 4; ++p) {          // s=1, n=8
        float2 A = a[p], B = a[p + 4];
        float2 d = csub(A, B);
        u[2 * p] = cadd(A, B);
        float2 w = (p == 0) ? make_float2(1.f, 0.f)
                 : (p == 1) ? make_float2(C, S * C)
                 : (p == 2) ? make_float2(0.f, S)
                            : make_float2(-C, S * C);
        u[2 * p + 1] = cmul(d, w);
    }
#pragma unroll
    for (int tt = 0; tt < 4; ++tt) {       // s=2, n=4
        int p = tt >> 1, q = tt & 1;
        float2 A = u[q + 2 * p], B = u[q + 2 * p + 4];
        float2 d = csub(A, B);
        v[q + 4 * p] = cadd(A, B);
        v[q + 4 * p + 2] = (p == 0) ? d : cmul(d, make_float2(0.f, S));
    }
#pragma unroll
    for (int q = 0; q < 4; ++q) {          // s=4, n=2
        float2 A = v[q], B = v[q + 4];
        y[q] = cadd(A, B);
        y[q + 4] = csub(A, B);
    }
}

// 512-pt radix-8 Stockham FFT; 64 threads per FFT, 8 elems/thread.
// In/out in registers: x[e] = element (t + 64e); output x[e] = bin (t + 64e).
// 2 __syncthreads per call.
template <int SIGN>
__device__ __forceinline__ void fft512_r8(float2* x, float2* sA, float2* sB, int t) {
    float2 y[8];
    // stage 0: s=1, n=512, p=t, q=0
    dft8<SIGN>(x, y);
    {
        float base = (float)SIGN * 0.012271846303085130f * (float)t;  // 2π/512 * t
#pragma unroll
        for (int e = 1; e < 8; ++e) {
            float sn, cs;
            __sincosf(base * (float)e, &sn, &cs);
            y[e] = cmul(y[e], make_float2(cs, sn));
        }
#pragma unroll
        for (int e = 0; e < 8; ++e) sA[PAD(8 * t + e)] = y[e];
    }
    __syncthreads();
    // stage 1: s=8, n=64, p=t>>3, q=t&7
#pragma unroll
    for (int e = 0; e < 8; ++e) x[e] = sA[PAD(t + 64 * e)];
    dft8<SIGN>(x, y);
    {
        int p = t >> 3, q = t & 7;
        float base = (float)SIGN * 0.098174770424681f * (float)p;      // 2π/64 * p
#pragma unroll
        for (int e = 1; e < 8; ++e) {
            float sn, cs;
            __sincosf(base * (float)e, &sn, &cs);
            y[e] = cmul(y[e], make_float2(cs, sn));
        }
        int wb = 8 * t - 7 * q;
#pragma unroll
        for (int e = 0; e < 8; ++e) sB[PAD(wb + 8 * e)] = y[e];
    }
    __syncthreads();
    // stage 2: s=64, p=0, q=t — no twiddle; output in natural order at (t+64e)
#pragma unroll
    for (int e = 0; e < 8; ++e) x[e] = sB[PAD(t + 64 * e)];
    dft8<SIGN>(x, y);
#pragma unroll
    for (int e = 0; e < 8; ++e) x[e] = y[e];
}

// Transfer function of 1000 Jacobi iterations (phi0 = B), incl. 1/N^2.
__device__ __forceinline__ float jacobi_T(int ki, int kj) {
    const float invN2 = 1.0f / 262144.0f;
    float sa = sinf(0.0061359231515f * (float)ki);   // sin(pi*ki/512)
    float sb = sinf(0.0061359231515f * (float)kj);
    float oms = sa * sa + sb * sb;                   // 1 - s, no cancellation
    if (oms <= 0.0f) return -249.0f * invN2;
    float arg = 500.0f * log1pf(-oms * (2.0f - oms));  // log(s^1000)
    float s1000 = (arg < -87.0f) ? 0.0f : expf(arg);
    return (s1000 - (1.0f - s1000) / (4.0f * oms)) * invN2;
}

// ---------------------------------------------------------------- kernels
__global__ void k_partial(const float* __restrict__ X, const float* __restrict__ F) {
    int id = blockIdx.x * blockDim.x + threadIdx.x;
    if (id >= NPLANE) return;
    int i = id >> 9, j = id & MASK;
    int im = (i - 1) & MASK, ip = (i + 1) & MASK;
    int jm = (j - 1) & MASK, jp = (j + 1) & MASK;

    float u = X[id];
    float v = X[NPLANE + id];
    const float NU = 0.1f;
#pragma unroll
    for (int c = 0; c < 2; ++c) {
        const float* xc = X + c * NPLANE;
        float ctr = xc[id];
        float up = xc[im * W + j];
        float dn = xc[ip * W + j];
        float lf = xc[i * W + jm];
        float rt = xc[i * W + jp];
        float dx = (dn - up) * 0.5f;
        float dy = (rt - lf) * 0.5f;
        float lap = (up + dn + lf + rt) - 4.0f * ctr;
        g_partial[c * NPLANE + id] = -(u * dx + v * dy) + NU * lap + F[c * NPLANE + id];
    }
}

// Rows forward: compute B inline from g_partial, FFT along j -> g_Fhat.
__global__ void __launch_bounds__(NTH) k_rows_fwd() {
    __shared__ float2 sm[2 * 4 * FSTRIDE];
    int f = threadIdx.x >> 6, t = threadIdx.x & 63;
    int r = blockIdx.x * 4 + f;
    float2* sA = sm + f * FSTRIDE;
    float2* sB = sm + (4 + f) * FSTRIDE;
    const float* p0 = g_partial;
    const float* p1 = g_partial + NPLANE;
    int rp = (r + 1) & MASK, rm = (r - 1) & MASK;

    float2 x[8];
#pragma unroll
    for (int e = 0; e < 8; ++e) {
        int j = t + 64 * e;
        int jp = (j + 1) & MASK, jm = (j - 1) & MASK;
        // RHO/(2*DX*DT) = 5
        float b = ((p0[rp * W + j] - p0[rm * W + j]) + (p1[r * W + jp] - p1[r * W + jm])) * 5.0f;
        x[e] = make_float2(b, 0.0f);
    }
    fft512_r8<-1>(x, sA, sB, t);
#pragma unroll
    for (int e = 0; e < 8; ++e) g_Fhat[r * W + t + 64 * e] = x[e];
}

// Columns: fwd FFT along i, multiply by T*(−sy + i*sx)/N^2, inverse FFT along i.
__global__ void __launch_bounds__(NTH) k_cols() {
    __shared__ float2 sm[2 * 4 * FSTRIDE];
    int f = threadIdx.x & 3, t = threadIdx.x >> 2;
    int c = blockIdx.x * 4 + f;
    float2* sA = sm + f * FSTRIDE;
    float2* sB = sm + (4 + f) * FSTRIDE;

    float2 x[8];
#pragma unroll
    for (int e = 0; e < 8; ++e) x[e] = g_Fhat[(t + 64 * e) * W + c];
    fft512_r8<-1>(x, sA, sB, t);

    float sy = __sinf(0.012271846303085130f * (float)c);   // sin(2π kj/512)
#pragma unroll
    for (int e = 0; e < 8; ++e) {
        int ki = t + 64 * e;
        float Tv = jacobi_T(ki, c);
        float sx = __sinf(0.012271846303085130f * (float)ki);
        x[e] = cmul(x[e], make_float2(-Tv * sy, Tv * sx));  // Zhat = phi_hat*(i*sx - sy)
    }
    fft512_r8<1>(x, sA, sB, t);
#pragma unroll
    for (int e = 0; e < 8; ++e) g_Fhat[(t + 64 * e) * W + c] = x[e];
}

// Rows inverse + epilogue: Z = gx + i*gy ; out[c] = partial[c] - (Re,Im)Z.
__global__ void __launch_bounds__(NTH) k_rows_inv_out(float* __restrict__ out) {
    __shared__ float2 sm[2 * 4 * FSTRIDE];
    int f = threadIdx.x >> 6, t = threadIdx.x & 63;
    int r = blockIdx.x * 4 + f;
    float2* sA = sm + f * FSTRIDE;
    float2* sB = sm + (4 + f) * FSTRIDE;

    float2 x[8];
#pragma unroll
    for (int e = 0; e < 8; ++e) x[e] = g_Fhat[r * W + t + 64 * e];
    fft512_r8<1>(x, sA, sB, t);
#pragma unroll
    for (int e = 0; e < 8; ++e) {
        int id = r * W + t + 64 * e;
        out[id]          = g_partial[id]          - x[e].x;
        out[NPLANE + id] = g_partial[NPLANE + id] - x[e].y;
    }
}

extern "C" void kernel_launch(void* const* d_in, const int* in_sizes, int n_in,
                              void* d_out, int out_size) {
    const float* X = (const float*)d_in[1];
    const float* F = (const float*)d_in[2];
    float* out = (float*)d_out;

    k_partial<<<NPLANE / NTH, NTH>>>(X, F);
    k_rows_fwd<<<H / 4, NTH>>>();
    k_cols<<<W / 4, NTH>>>();
    k_rows_inv_out<<<H / 4, NTH>>>(out);
}